// round 9
// baseline (speedup 1.0000x reference)
#include <cuda_runtime.h>
#include <cuda_fp16.h>
#include <cstdint>

// ---------------------------------------------------------------------------
// Problem constants
// ---------------------------------------------------------------------------
#define D_DIM 128
#define O_DIM 128
#define R_DIM 4
#define N_MAX 100000
#define E_MAX 400000

// Scratch
__device__ __half g_Yh[(size_t)R_DIM * N_MAX * O_DIM];   // Y fp16 [R][N][O]
__device__ __half g_xh[(size_t)N_MAX * D_DIM];           // x fp16 [N][D]
__device__ __half g_WhT[(size_t)R_DIM * O_DIM * D_DIM];  // W^T fp16 [R][O][D]

// CSR build scratch
__device__ int   g_counts[N_MAX];
__device__ int   g_off[N_MAX + 1];
__device__ int   g_cur[N_MAX];
__device__ uint2 g_erec[(size_t)R_DIM * E_MAX];          // {col | r<<17, val bits}

// ---------------------------------------------------------------------------
// Pre-pass: x -> fp16
// ---------------------------------------------------------------------------
__global__ void __launch_bounds__(256)
convert_x(const float* __restrict__ x, int N)
{
    int idx = blockIdx.x * blockDim.x + threadIdx.x;
    int total = N * (D_DIM / 4);
    if (idx >= total) return;
    float4 v = *reinterpret_cast<const float4*>(x + (size_t)idx * 4);
    __half2 h01 = __floats2half2_rn(v.x, v.y);
    __half2 h23 = __floats2half2_rn(v.z, v.w);
    uint2 pk = make_uint2(*reinterpret_cast<uint32_t*>(&h01),
                          *reinterpret_cast<uint32_t*>(&h23));
    *reinterpret_cast<uint2*>(g_xh + (size_t)idx * 4) = pk;
}

// Pre-pass: W[r*128+d][o] -> WhT[r][o][d], fp16, smem tile transpose
__global__ void __launch_bounds__(1024)
convert_Wt(const float* __restrict__ W)
{
    __shared__ float s[32][33];
    const int r  = blockIdx.y;
    const int td = (blockIdx.x >> 2) * 32;
    const int to = (blockIdx.x & 3) * 32;
    const int tx = threadIdx.x & 31;
    const int ty = threadIdx.x >> 5;
    s[ty][tx] = W[(size_t)(r * D_DIM + td + ty) * O_DIM + to + tx];
    __syncthreads();
    g_WhT[(size_t)r * O_DIM * D_DIM + (size_t)(to + ty) * D_DIM + td + tx] =
        __float2half_rn(s[tx][ty]);
}

// ---------------------------------------------------------------------------
// CSR build
// ---------------------------------------------------------------------------
__global__ void __launch_bounds__(256)
zero_counts(int N)
{
    int idx = blockIdx.x * blockDim.x + threadIdx.x;
    if (idx < N) g_counts[idx] = 0;
}

__global__ void __launch_bounds__(256)
hist_kernel(const int* __restrict__ rows_flat, int total)
{
    int idx = blockIdx.x * blockDim.x + threadIdx.x;
    if (idx < total) atomicAdd(&g_counts[rows_flat[idx]], 1);
}

// Single-CTA scan: counts -> off/cur (exclusive), off[N] = total.
__global__ void __launch_bounds__(1024)
scan_kernel(int N)
{
    __shared__ int sdata[1024];
    const int tid = threadIdx.x;
    const int chunk = (N + 1023) >> 10;
    const int lo = tid * chunk;
    const int hi = min(lo + chunk, N);

    int s = 0;
    for (int i = lo; i < hi; i++) s += g_counts[i];
    sdata[tid] = s;
    __syncthreads();
    for (int d = 1; d < 1024; d <<= 1) {
        int v = (tid >= d) ? sdata[tid - d] : 0;
        __syncthreads();
        sdata[tid] += v;
        __syncthreads();
    }
    int run = (tid > 0) ? sdata[tid - 1] : 0;   // exclusive prefix
    for (int i = lo; i < hi; i++) {
        g_off[i] = run;
        g_cur[i] = run;
        run += g_counts[i];
    }
    if (tid == 1023) g_off[N] = sdata[1023];
}

__global__ void __launch_bounds__(256)
fill_kernel(const int* __restrict__ rows_flat, const int* __restrict__ cols_flat,
            const float* __restrict__ vals_flat, int E, int total)
{
    int idx = blockIdx.x * blockDim.x + threadIdx.x;
    if (idx >= total) return;
    int row = rows_flat[idx];
    int col = cols_flat[idx];
    float v = vals_flat[idx];
    int r   = idx / E;
    int pos = atomicAdd(&g_cur[row], 1);
    g_erec[pos] = make_uint2((uint32_t)col | ((uint32_t)r << 17), __float_as_uint(v));
}

// ---------------------------------------------------------------------------
// GEMM: per CTA 128 M-rows x 128 out-cols (one relation), fp16 single pass.
// ---------------------------------------------------------------------------
#define SM_A 0
#define SM_B 32768
#define SMEM_TOTAL 65536

__device__ __forceinline__ uint32_t smem_u32(const void* p) {
    uint32_t a;
    asm("{ .reg .u64 t; cvta.to.shared.u64 t, %1; cvt.u32.u64 %0, t; }" : "=r"(a) : "l"(p));
    return a;
}
__device__ __forceinline__ uint32_t offAB(int row, int k) {
    return (uint32_t)row * 256u + (uint32_t)(((k >> 3) ^ (row & 7)) * 16) + (uint32_t)((k & 7) * 2);
}
__device__ __forceinline__ void ldsm4(uint32_t* r, uint32_t addr) {
    asm volatile("ldmatrix.sync.aligned.m8n8.x4.shared.b16 {%0,%1,%2,%3}, [%4];"
                 : "=r"(r[0]), "=r"(r[1]), "=r"(r[2]), "=r"(r[3]) : "r"(addr));
}
__device__ __forceinline__ void mma16816(float* c, const uint32_t* a, uint32_t b0, uint32_t b1) {
    asm volatile("mma.sync.aligned.m16n8k16.row.col.f32.f16.f16.f32 "
                 "{%0,%1,%2,%3}, {%4,%5,%6,%7}, {%8,%9}, {%0,%1,%2,%3};"
                 : "+f"(c[0]), "+f"(c[1]), "+f"(c[2]), "+f"(c[3])
                 : "r"(a[0]), "r"(a[1]), "r"(a[2]), "r"(a[3]), "r"(b0), "r"(b1));
}

__global__ void __launch_bounds__(256, 2)
gemm_fp16(int N)
{
    extern __shared__ char smem[];
    const uint32_t sb = smem_u32(smem);
    const int tid    = threadIdx.x;
    const int lane   = tid & 31;
    const int wid    = tid >> 5;
    const int warp_m = wid >> 2;
    const int warp_n = wid & 3;
    const int r      = blockIdx.x;
    const int m0     = blockIdx.y * 128;

    {
        const __half* Wt = g_WhT + (size_t)r * O_DIM * D_DIM;
#pragma unroll
        for (int i = 0; i < 8; i++) {
            int t   = tid + i * 256;
            int row = t >> 4;
            int c   = t & 15;
            uint32_t dsw = (uint32_t)row * 256u + (uint32_t)((c ^ (row & 7)) * 16);
            int gm  = m0 + row;
            int gmc = (gm < N) ? gm : (N - 1);
            uint4 va = *reinterpret_cast<const uint4*>(g_xh + (size_t)gmc * D_DIM + c * 8);
            uint4 vb = *reinterpret_cast<const uint4*>(Wt + (size_t)row * D_DIM + c * 8);
            *reinterpret_cast<uint4*>(smem + SM_A + dsw) = va;
            *reinterpret_cast<uint4*>(smem + SM_B + dsw) = vb;
        }
    }
    __syncthreads();

    float acc[4][4][4];
#pragma unroll
    for (int mt = 0; mt < 4; mt++)
#pragma unroll
        for (int nt = 0; nt < 4; nt++)
#pragma unroll
            for (int q = 0; q < 4; q++) acc[mt][nt][q] = 0.f;

    const int a_row = warp_m * 64 + (lane & 15);
    const int b_row = warp_n * 32 + (lane & 15);
    const int khalf = (lane >> 4) * 8;
    const uint32_t As = sb + SM_A, Bs = sb + SM_B;

#pragma unroll
    for (int ks = 0; ks < 8; ks++) {
        const int k0 = ks * 16;
        uint32_t a[4][4], b[2][4];
#pragma unroll
        for (int mt = 0; mt < 4; mt++)
            ldsm4(a[mt], As + offAB(a_row + mt * 16, k0 + khalf));
#pragma unroll
        for (int np = 0; np < 2; np++)
            ldsm4(b[np], Bs + offAB(b_row + np * 16, k0 + khalf));
#pragma unroll
        for (int mt = 0; mt < 4; mt++) {
#pragma unroll
            for (int nt = 0; nt < 4; nt++) {
                const uint32_t* bb = b[nt >> 1];
                uint32_t b0 = (nt & 1) ? bb[1] : bb[0];
                uint32_t b1 = (nt & 1) ? bb[3] : bb[2];
                mma16816(acc[mt][nt], a[mt], b0, b1);
            }
        }
    }

    __half* Yr = g_Yh + (size_t)r * N_MAX * O_DIM;
#pragma unroll
    for (int mt = 0; mt < 4; mt++) {
        int gm0 = m0 + warp_m * 64 + mt * 16 + (lane >> 2);
#pragma unroll
        for (int nt = 0; nt < 4; nt++) {
            int o = warp_n * 32 + nt * 8 + (lane & 3) * 2;
            if (gm0 < N) {
                __half2 h = __floats2half2_rn(acc[mt][nt][0], acc[mt][nt][1]);
                *reinterpret_cast<uint32_t*>(Yr + (size_t)gm0 * O_DIM + o) =
                    *reinterpret_cast<uint32_t*>(&h);
            }
            if (gm0 + 8 < N) {
                __half2 h = __floats2half2_rn(acc[mt][nt][2], acc[mt][nt][3]);
                *reinterpret_cast<uint32_t*>(Yr + (size_t)(gm0 + 8) * O_DIM + o) =
                    *reinterpret_cast<uint32_t*>(&h);
            }
        }
    }
}

// ---------------------------------------------------------------------------
// Gather: one warp per output row; fp32 register accumulation, no atomics.
// ---------------------------------------------------------------------------
__global__ void __launch_bounds__(256)
gather_kernel(float* __restrict__ out, int N)
{
    const int lane = threadIdx.x & 31;
    const int gw   = (blockIdx.x * blockDim.x + threadIdx.x) >> 5;
    const int nw   = (gridDim.x * blockDim.x) >> 5;

    for (int row = gw; row < N; row += nw) {
        const int e0 = g_off[row];
        const int e1 = g_off[row + 1];
        float4 acc = make_float4(0.f, 0.f, 0.f, 0.f);

        for (int eb = e0; eb < e1; eb += 32) {
            int cnt = min(32, e1 - eb);
            uint2 er = (eb + lane < e1) ? g_erec[eb + lane] : make_uint2(0u, 0u);
#pragma unroll 4
            for (int j = 0; j < cnt; j++) {
                uint32_t p = __shfl_sync(0xffffffffu, er.x, j);
                float    v = __uint_as_float(__shfl_sync(0xffffffffu, er.y, j));
                const __half* Yp = g_Yh +
                    ((size_t)(p >> 17) * N_MAX + (p & 0x1FFFFu)) * O_DIM + lane * 4;
                uint2 q = *reinterpret_cast<const uint2*>(Yp);
                __half2 h0 = *reinterpret_cast<__half2*>(&q.x);
                __half2 h1 = *reinterpret_cast<__half2*>(&q.y);
                float2 f0 = __half22float2(h0);
                float2 f1 = __half22float2(h1);
                acc.x = fmaf(v, f0.x, acc.x);
                acc.y = fmaf(v, f0.y, acc.y);
                acc.z = fmaf(v, f1.x, acc.z);
                acc.w = fmaf(v, f1.y, acc.w);
            }
        }
        *reinterpret_cast<float4*>(out + (size_t)row * O_DIM + lane * 4) = acc;
    }
}

// ---------------------------------------------------------------------------
// kernel_launch
// ---------------------------------------------------------------------------
extern "C" void kernel_launch(void* const* d_in, const int* in_sizes, int n_in,
                              void* d_out, int out_size)
{
    const float* x        = (const float*)d_in[0];
    const int*   edge_row = (const int*)  d_in[1];
    const int*   edge_col = (const int*)  d_in[2];
    const float* edge_val = (const float*)d_in[3];
    const float* W        = (const float*)d_in[4];
    float*       out      = (float*)d_out;

    const int N = in_sizes[0] / D_DIM;          // 100000
    const int E = in_sizes[1] / R_DIM;          // 400000
    const int RE = R_DIM * E;

    cudaFuncSetAttribute(gemm_fp16, cudaFuncAttributeMaxDynamicSharedMemorySize, SMEM_TOTAL);

    // CSR build (self-contained per call: zero -> hist -> scan -> fill)
    zero_counts<<<(N + 255) / 256, 256>>>(N);
    hist_kernel<<<(RE + 255) / 256, 256>>>(edge_row, RE);
    scan_kernel<<<1, 1024>>>(N);
    fill_kernel<<<(RE + 255) / 256, 256>>>(edge_row, edge_col, edge_val, E, RE);

    // Dense phase
    {
        int total = N * (D_DIM / 4);
        convert_x<<<(total + 255) / 256, 256>>>(x, N);
        dim3 gw(16, R_DIM);
        convert_Wt<<<gw, 1024>>>(W);
    }
    {
        dim3 grid(R_DIM, (N + 127) / 128);
        gemm_fp16<<<grid, 256, SMEM_TOTAL>>>(N);
    }

    // Sparse phase: atomic-free gather
    gather_kernel<<<2048, 256>>>(out, N);
}